// round 2
// baseline (speedup 1.0000x reference)
#include <cuda_runtime.h>
#include <stdint.h>

// Problem constants (fixed shapes from reference)
#define NB 32
#define NS 32
#define NW 30
#define NE 300
#define NEV 75                  // float4 per embedding row (300 floats)
#define NSENT (NB * NS)         // 1024 sentences
#define EMB_ELEMS (NSENT * NW * NE)          // 9,216,000
#define OFF_SHARE  EMB_ELEMS                 // share_enc_embedded starts here
#define OFF_MASK   (2 * EMB_ELEMS)           // 18,432,000
#define OFF_WMASK  (OFF_MASK + NSENT * NW)   // 18,462,720
#define OFF_SMASK  (OFF_WMASK + NSENT * NW)  // 18,493,440

__global__ __launch_bounds__(256, 8) void embed_fused_kernel(
    const int* __restrict__ input_var,        // [1024*30] int32 tokens (JAX x64 off)
    const float* __restrict__ W_emb,          // [50000*300]
    float* __restrict__ out)
{
    const int sent = blockIdx.x;   // 0..1023  (= b*32 + s)
    const int tid  = threadIdx.x;

    __shared__ int s_tok[NW];
    __shared__ int s_tmp[NW];

    // Stage tokens for this sentence
    if (tid < NW) {
        s_tok[tid] = input_var[sent * NW + tid];
    }
    __syncthreads();

    // Per-token truncation keep-mask (keep up to FIRST zero, inclusive-product)
    // mask == keep exactly (keep[w] implies tok[w]!=0).
    if (tid < NW) {
        bool keep = true;
        #pragma unroll
        for (int k = 0; k <= tid; k++) keep = keep && (s_tok[k] != 0);
        const int t = s_tok[tid];
        s_tmp[tid] = keep ? t : 0;
        out[OFF_MASK  + sent * NW + tid] = keep ? 1.0f : 0.0f;
        out[OFF_WMASK + sent * NW + tid] = (t != 0) ? 1.0f : 0.0f;
    }
    if (tid == 0) {
        bool any = false;
        #pragma unroll
        for (int k = 0; k < NW; k++) any = any || (s_tok[k] != 0);
        out[OFF_SMASK + sent] = any ? 1.0f : 0.0f;
    }
    __syncthreads();

    // Gather-copy: 30 rows x 75 float4 = 2250 vec4 per output region.
    // Load each row once; reuse for the share output unless truncated.
    const float4* __restrict__ emb4 = (const float4*)W_emb;
    float4* __restrict__ out_e = (float4*)out + (size_t)sent * (NW * NEV);
    float4* __restrict__ out_s = (float4*)(out + OFF_SHARE) + (size_t)sent * (NW * NEV);

    #pragma unroll 2
    for (int v = tid; v < NW * NEV; v += 256) {
        const int w = v / NEV;
        const int j = v - w * NEV;
        const int t  = s_tok[w];
        const int tp = s_tmp[w];
        float4 val = emb4[(size_t)t * NEV + j];
        out_e[v] = val;
        if (tp != t) val = emb4[(size_t)tp * NEV + j];  // rare: truncated token -> row 0
        out_s[v] = val;
    }
}

extern "C" void kernel_launch(void* const* d_in, const int* in_sizes, int n_in,
                              void* d_out, int out_size) {
    const int*   input_var = (const int*)d_in[0];
    const float* W_emb     = (const float*)d_in[1];
    float*       out       = (float*)d_out;

    embed_fused_kernel<<<NSENT, 256>>>(input_var, W_emb, out);
}

// round 3
// speedup vs baseline: 1.1402x; 1.1402x over previous
#include <cuda_runtime.h>
#include <stdint.h>

// Problem constants (fixed shapes from reference)
#define NB 32
#define NS 32
#define NW 30
#define NE 300
#define NEV 75                   // float4 per embedding row (300 floats)
#define NSENT (NB * NS)          // 1024 sentences
#define EMB_ELEMS (NSENT * NW * NE)          // 9,216,000
#define OFF_SHARE  EMB_ELEMS
#define OFF_MASK   (2 * EMB_ELEMS)           // 18,432,000
#define OFF_WMASK  (OFF_MASK + NSENT * NW)   // 18,462,720
#define OFF_SMASK  (OFF_WMASK + NSENT * NW)  // 18,493,440

#define HALF_ROWS 15
#define HALF_VEC  (HALF_ROWS * NEV)          // 1125 float4 per half-sentence
#define NITER     5                          // ceil(1125/256)

__global__ __launch_bounds__(256) void embed_fused_kernel(
    const int* __restrict__ input_var,        // [1024*30] int32 tokens
    const float* __restrict__ W_emb,          // [50000*300]
    float* __restrict__ out)
{
    const int sent = blockIdx.x >> 1;   // 0..1023
    const int half = blockIdx.x & 1;    // 0: rows 0-14, 1: rows 15-29
    const int tid  = threadIdx.x;

    __shared__ int s_tok[NW];
    __shared__ int s_tmp[NW];

    if (tid < NW) s_tok[tid] = input_var[sent * NW + tid];
    __syncthreads();

    // keep-mask: keep tokens strictly before the first zero (cumprod of nonzero)
    if (tid < NW) {
        bool keep = true;
        #pragma unroll
        for (int k = 0; k <= tid; k++) keep = keep && (s_tok[k] != 0);
        const int t = s_tok[tid];
        s_tmp[tid] = keep ? t : 0;
        if (half == 0) {
            out[OFF_MASK  + sent * NW + tid] = keep ? 1.0f : 0.0f;
            out[OFF_WMASK + sent * NW + tid] = (t != 0) ? 1.0f : 0.0f;
        }
    }
    if (half == 0 && tid == 0) {
        bool any = false;
        #pragma unroll
        for (int k = 0; k < NW; k++) any = any || (s_tok[k] != 0);
        out[OFF_SMASK + sent] = any ? 1.0f : 0.0f;
    }
    __syncthreads();

    const float4* __restrict__ emb4 = (const float4*)W_emb;
    float4* __restrict__ out_e = (float4*)out
        + (size_t)sent * (NW * NEV) + half * HALF_VEC;
    float4* __restrict__ out_s = (float4*)(out + OFF_SHARE)
        + (size_t)sent * (NW * NEV) + half * HALF_VEC;

    // Phase 1: batch 5 independent gather loads per thread (high MLP)
    float4 vals[NITER];
    #pragma unroll
    for (int i = 0; i < NITER; i++) {
        const int v = tid + i * 256;
        if (v < HALF_VEC) {
            const int wl = v / NEV;
            const int j  = v - wl * NEV;
            const int t  = s_tok[half * HALF_ROWS + wl];
            vals[i] = emb4[(size_t)t * NEV + j];
        }
    }

    // Phase 2: streaming stores; rare truncated-token reload (predicated)
    #pragma unroll
    for (int i = 0; i < NITER; i++) {
        const int v = tid + i * 256;
        if (v < HALF_VEC) {
            const int wl = v / NEV;
            const int j  = v - wl * NEV;
            const int w  = half * HALF_ROWS + wl;
            __stcs(&out_e[v], vals[i]);
            float4 x = vals[i];
            const int t  = s_tok[w];
            const int tp = s_tmp[w];
            if (tp != t) x = emb4[(size_t)tp * NEV + j];  // rare: -> row 0
            __stcs(&out_s[v], x);
        }
    }
}

extern "C" void kernel_launch(void* const* d_in, const int* in_sizes, int n_in,
                              void* d_out, int out_size) {
    const int*   input_var = (const int*)d_in[0];
    const float* W_emb     = (const float*)d_in[1];
    float*       out       = (float*)d_out;

    embed_fused_kernel<<<2 * NSENT, 256>>>(input_var, W_emb, out);
}